// round 2
// baseline (speedup 1.0000x reference)
#include <cuda_runtime.h>

// out == broadcast(ln_beta[0]) exactly (LayerNorm over a size-1 dim:
// mu == h, h - mu == 0, var == 0 -> out = 0 * rsqrt(eps) * gamma + beta).
// The gather + 4-layer MLP is algebraically dead.
//
// R1 lesson: the 12.8 MB output lives entirely in L2 across graph replays
// (DRAM=0%), so this is issue-bound, not BW-bound. Kill the grid-stride
// loop: exact-fit grid, 4 independent unrolled STG.128 per thread.

#define THREADS 256
#define VEC_PER_THREAD 4

__global__ void __launch_bounds__(THREADS)
decoder_fill_kernel(const float* __restrict__ ln_beta,
                    float4* __restrict__ out4,
                    unsigned int n4,
                    unsigned int stride) {
    const float b = __ldg(ln_beta);
    const float4 v = make_float4(b, b, b, b);

    unsigned int i = blockIdx.x * THREADS + threadIdx.x;

#pragma unroll
    for (int k = 0; k < VEC_PER_THREAD; ++k) {
        unsigned int j = i + (unsigned int)k * stride;
        if (j < n4) out4[j] = v;
    }
}

// Scalar tail kernel only needed if out_size % 4 != 0 (it isn't for 3.2M,
// but keep the launch general and branch on host side — host-side branch on
// a host-known constant is graph-capture safe).
__global__ void decoder_fill_tail(const float* __restrict__ ln_beta,
                                  float* __restrict__ out,
                                  int start, int n) {
    int i = start + threadIdx.x;
    if (i < n) out[i] = __ldg(ln_beta);
}

extern "C" void kernel_launch(void* const* d_in, const int* in_sizes, int n_in,
                              void* d_out, int out_size) {
    const float* ln_beta = (const float*)d_in[n_in - 1];
    float* out = (float*)d_out;

    unsigned int n4 = (unsigned int)(out_size >> 2);
    // Exact-fit single wave: total threads T = ceil(n4 / VEC_PER_THREAD),
    // each thread does VEC_PER_THREAD coalesced STG.128 at stride T.
    unsigned int total_threads = (n4 + VEC_PER_THREAD - 1) / VEC_PER_THREAD;
    unsigned int blocks = (total_threads + THREADS - 1) / THREADS;
    unsigned int stride = blocks * THREADS;

    decoder_fill_kernel<<<blocks, THREADS>>>(ln_beta, (float4*)out, n4, stride);

    int tail_start = (int)(n4 << 2);
    if (tail_start < out_size) {
        decoder_fill_tail<<<1, 32>>>(ln_beta, out, tail_start, out_size);
    }
}